// round 10
// baseline (speedup 1.0000x reference)
#include <cuda_runtime.h>
#include <cstdint>
#include <cstddef>

#define Tn 1024
#define Bn 512
#define Hn 128
#define In 64
#define G3 384

// ---------------------------------------------------------------------------
// Packed f32x2 FMA (Blackwell): d.lo += a.lo*b.lo ; d.hi += a.hi*b.hi
// ---------------------------------------------------------------------------
__device__ __forceinline__ void ffma2(unsigned long long& d,
                                      const unsigned long long a,
                                      const unsigned long long b) {
    asm("fma.rn.f32x2 %0, %1, %2, %0;" : "+l"(d) : "l"(a), "l"(b));
}

__device__ __forceinline__ float hsum2(unsigned long long v) {
    float lo, hi;
    asm("mov.b64 {%0, %1}, %2;" : "=f"(lo), "=f"(hi) : "l"(v));
    return lo + hi;
}

__device__ __forceinline__ float sigf(float x) {
    return __fdividef(1.0f, 1.0f + __expf(-x));
}
__device__ __forceinline__ float tanh_fast(float x) {
    return 1.0f - __fdividef(2.0f, 1.0f + __expf(2.0f * x));
}

// ---------------------------------------------------------------------------
// Fused GRU: input projection (1 step lookahead) + recurrence + final FC.
// 128 blocks x 4 batches, 256 threads. Thread: j = tid>>1, half = tid&1.
// Recurrence: r,z gate W row-halves in REGISTERS; n gate row-half in smem
// (per-thread packed, stride 68 -> conflict-free). h double-buffered; one
// barrier/step; cross-half reduction via shfl_xor(.,1).
// Input projection xg(t+1) computed inline: thread covers its 3 gate rows x
// its 2 batches x full k=64, W_ih from smem [384][68], x from gmem (L1
// broadcast). Result carried in 6 registers into the next iteration.
// ---------------------------------------------------------------------------
#define HROW 136
__device__ __forceinline__ int hpos(int k) { return k + ((k >> 6) << 2); }

// dynamic smem layout (floats)
#define SM_WIH   0                    // [384][68]  = 26112
#define SM_WN    (384 * 68)           // [256][68]  = 17408 (per-thread packed)
#define SM_HS    (SM_WN + 256 * 68)   // [2][4][HROW] = 1088
#define SM_FLOATS (SM_HS + 2 * 4 * HROW)
#define SM_BYTES (SM_FLOATS * 4)

__global__ void __launch_bounds__(256, 1)
gru_fused(const float* __restrict__ x,
          const float* __restrict__ Wih,
          const float* __restrict__ Whh,
          const float* __restrict__ bih,
          const float* __restrict__ bhh,
          const float* __restrict__ Wfc,
          const float* __restrict__ bfc,
          float* __restrict__ out) {
    extern __shared__ __align__(16) float sm[];
    float* wih_s = sm + SM_WIH;
    float* wn_s = sm + SM_WN;
    float* hs = sm + SM_HS;

    const int tid = threadIdx.x;
    const int j = tid >> 1;
    const int half = tid & 1;
    const int b0 = blockIdx.x * 4;

    // ---- prologue: fill smem ----
    // W_ih [384][68] padded, coalesced float4
    #pragma unroll
    for (int i = tid; i < 384 * 16; i += 256) {
        int row = i >> 4, c4 = i & 15;
        *(float4*)(wih_s + row * 68 + c4 * 4) = ((const float4*)Wih)[i];
    }
    // n-gate W_hh row-half, per-thread packed [tid][68]
    {
        const float4* src = (const float4*)(Whh + (size_t)(256 + j) * 128 + half * 64);
        #pragma unroll
        for (int kk = 0; kk < 16; kk++)
            *(float4*)(wn_s + tid * 68 + kk * 4) = src[kk];
    }
    for (int i = tid; i < 4 * HROW; i += 256) hs[i] = 0.0f;

    // r,z gate W row-halves -> registers (2 x 16 ull2 = 64 regs)
    ulonglong2 wrr[16], wzr[16];
    {
        const ulonglong2* wr_g = (const ulonglong2*)(Whh + (size_t)j * 128 + half * 64);
        const ulonglong2* wz_g = (const ulonglong2*)(Whh + (size_t)(j + 128) * 128 + half * 64);
        #pragma unroll
        for (int kk = 0; kk < 16; kk++) {
            wrr[kk] = wr_g[kk];
            wzr[kk] = wz_g[kk];
        }
    }
    const float bn = bhh[256 + j];                 // hidden n bias (inside r*())
    const float br = bih[j] + bhh[j];              // input-side r bias
    const float bz = bih[j + 128] + bhh[j + 128];  // input-side z bias
    const float bxn = bih[j + 256];                // input-side n bias
    float hold[2] = {0.f, 0.f};

    __syncthreads();

    // W_ih row pointers for this thread's 3 gate rows (full k=64)
    const ulonglong2* wi0 = (const ulonglong2*)(wih_s + j * 68);
    const ulonglong2* wi1 = (const ulonglong2*)(wih_s + (j + 128) * 68);
    const ulonglong2* wi2 = (const ulonglong2*)(wih_s + (j + 256) * 68);
    const ulonglong2* wnp = (const ulonglong2*)(wn_s + tid * 68);

    // x row pointers for this thread's 2 batches (advance 64 floats/step)
    const ulonglong2* xA = (const ulonglong2*)(x + ((size_t)(b0 + 2 * half) * Tn) * 64);
    const ulonglong2* xB = (const ulonglong2*)(x + ((size_t)(b0 + 2 * half + 1) * Tn) * 64);

    // ---- bootstrap: xg(t=0) ----
    float xr0, xz0, xn0, xr1, xz1, xn1;
    {
        unsigned long long xac[6] = {0, 0, 0, 0, 0, 0};
        #pragma unroll
        for (int kk = 0; kk < 16; kk++) {
            ulonglong2 w0 = wi0[kk], w1 = wi1[kk], w2 = wi2[kk];
            ulonglong2 a = xA[kk], b = xB[kk];
            ffma2(xac[0], w0.x, a.x); ffma2(xac[0], w0.y, a.y);
            ffma2(xac[1], w1.x, a.x); ffma2(xac[1], w1.y, a.y);
            ffma2(xac[2], w2.x, a.x); ffma2(xac[2], w2.y, a.y);
            ffma2(xac[3], w0.x, b.x); ffma2(xac[3], w0.y, b.y);
            ffma2(xac[4], w1.x, b.x); ffma2(xac[4], w1.y, b.y);
            ffma2(xac[5], w2.x, b.x); ffma2(xac[5], w2.y, b.y);
        }
        xr0 = hsum2(xac[0]) + br;
        xz0 = hsum2(xac[1]) + bz;
        xn0 = hsum2(xac[2]) + bxn;
        xr1 = hsum2(xac[3]) + br;
        xz1 = hsum2(xac[4]) + bz;
        xn1 = hsum2(xac[5]) + bxn;
    }

    for (int t = 0; t < Tn; t++) {
        const float* hrd = hs + (t & 1) * (4 * HROW);
        float* hwr = hs + ((t & 1) ^ 1) * (4 * HROW);

        // ---- lookahead input projection xg(t+1) (independent work that
        // fills the recurrence dot's latency gaps) ----
        unsigned long long xac[6] = {0, 0, 0, 0, 0, 0};
        const bool doxg = (t < Tn - 1);
        if (doxg) {
            const ulonglong2* xa = xA + (size_t)(t + 1) * 16;
            const ulonglong2* xb = xB + (size_t)(t + 1) * 16;
            #pragma unroll
            for (int kk = 0; kk < 16; kk++) {
                ulonglong2 w0 = wi0[kk], w1 = wi1[kk], w2 = wi2[kk];
                ulonglong2 a = xa[kk], b = xb[kk];
                ffma2(xac[0], w0.x, a.x); ffma2(xac[0], w0.y, a.y);
                ffma2(xac[1], w1.x, a.x); ffma2(xac[1], w1.y, a.y);
                ffma2(xac[2], w2.x, a.x); ffma2(xac[2], w2.y, a.y);
                ffma2(xac[3], w0.x, b.x); ffma2(xac[3], w0.y, b.y);
                ffma2(xac[4], w1.x, b.x); ffma2(xac[4], w1.y, b.y);
                ffma2(xac[5], w2.x, b.x); ffma2(xac[5], w2.y, b.y);
            }
        }

        // ---- recurrence dot: 3 gates x 4 batches over this k-half ----
        unsigned long long acc[3][4];
        #pragma unroll
        for (int g = 0; g < 3; g++)
            #pragma unroll
            for (int b = 0; b < 4; b++) acc[g][b] = 0ULL;

        const float* hbase = hrd + half * 68;
        #pragma unroll
        for (int kk = 0; kk < 16; kk++) {
            const ulonglong2 wr = wrr[kk], wz = wzr[kk];
            const ulonglong2 wn = wnp[kk];
            #pragma unroll
            for (int b = 0; b < 4; b++) {
                ulonglong2 hv = *(const ulonglong2*)(hbase + b * HROW + kk * 4);
                ffma2(acc[0][b], wr.x, hv.x); ffma2(acc[0][b], wr.y, hv.y);
                ffma2(acc[1][b], wz.x, hv.x); ffma2(acc[1][b], wz.y, hv.y);
                ffma2(acc[2][b], wn.x, hv.x); ffma2(acc[2][b], wn.y, hv.y);
            }
        }

        float s[3][4];
        #pragma unroll
        for (int g = 0; g < 3; g++)
            #pragma unroll
            for (int b = 0; b < 4; b++) s[g][b] = hsum2(acc[g][b]);

        // cross-half reduce-scatter with partner lane (tid^1)
        float tot[3][2];
        #pragma unroll
        for (int g = 0; g < 3; g++) {
            #pragma unroll
            for (int i = 0; i < 2; i++) {
                float keepv = half ? s[g][2 + i] : s[g][i];
                float sendv = half ? s[g][i] : s[g][2 + i];
                tot[g][i] = keepv + __shfl_xor_sync(0xFFFFFFFFu, sendv, 1);
            }
        }

        // gates for (j, b = 2*half + i) using xg(t) carried in registers
        {
            float r0g = sigf(xr0 + tot[0][0]);
            float z0g = sigf(xz0 + tot[1][0]);
            float n0g = tanh_fast(fmaf(r0g, tot[2][0] + bn, xn0));
            float h0n = fmaf(z0g, hold[0] - n0g, n0g);
            hold[0] = h0n;
            hwr[(2 * half + 0) * HROW + hpos(j)] = h0n;

            float r1g = sigf(xr1 + tot[0][1]);
            float z1g = sigf(xz1 + tot[1][1]);
            float n1g = tanh_fast(fmaf(r1g, tot[2][1] + bn, xn1));
            float h1n = fmaf(z1g, hold[1] - n1g, n1g);
            hold[1] = h1n;
            hwr[(2 * half + 1) * HROW + hpos(j)] = h1n;
        }

        // commit xg(t+1) into the carried registers
        if (doxg) {
            xr0 = hsum2(xac[0]) + br;
            xz0 = hsum2(xac[1]) + bz;
            xn0 = hsum2(xac[2]) + bxn;
            xr1 = hsum2(xac[3]) + br;
            xz1 = hsum2(xac[4]) + bz;
            xn1 = hsum2(xac[5]) + bxn;
        }

        __syncthreads();
    }

    // Final h is in buffer 0 (t=1023 writes buf (1023+1)&1 = 0).
    // FC: out[b][o] = h_T[b] . W_fc[o] + b_fc[o]
    if (tid < 4 * 51) {
        const int b = tid / 51, o = tid % 51;
        float a = bfc[o];
        const float* wf = Wfc + o * 128;
        const float* hp = hs + b * HROW;
        #pragma unroll 8
        for (int k = 0; k < 128; k++) a = fmaf(hp[hpos(k)], wf[k], a);
        out[(b0 + b) * 51 + o] = a;
    }
}

// ---------------------------------------------------------------------------
// Launch
// ---------------------------------------------------------------------------
extern "C" void kernel_launch(void* const* d_in, const int* in_sizes, int n_in,
                              void* d_out, int out_size) {
    const float* x    = (const float*)d_in[0];  // [512,1,1024,64]
    const float* Wih  = (const float*)d_in[1];  // [384,64]
    const float* Whh  = (const float*)d_in[2];  // [384,128]
    const float* bih  = (const float*)d_in[3];  // [384]
    const float* bhh  = (const float*)d_in[4];  // [384]
    const float* Wfc  = (const float*)d_in[5];  // [51,128]
    const float* bfc  = (const float*)d_in[6];  // [51]
    float* out = (float*)d_out;                 // [512,51]

    static int attr_done = 0;
    if (!attr_done) {
        cudaFuncSetAttribute(gru_fused,
                             cudaFuncAttributeMaxDynamicSharedMemorySize,
                             SM_BYTES);
        attr_done = 1;
    }

    gru_fused<<<128, 256, SM_BYTES>>>(x, Wih, Whh, bih, bhh, Wfc, bfc, out);
}

// round 11
// speedup vs baseline: 1.0573x; 1.0573x over previous
#include <cuda_runtime.h>
#include <cstdint>
#include <cstddef>

#define Tn 1024
#define Bn 512
#define Hn 128
#define In 64
#define G3 384

// 805 MB scratch for precomputed input-side gate projections: xg[b][t][g]
__device__ float g_xg[(size_t)Bn * Tn * G3];

// ---------------------------------------------------------------------------
// Packed f32x2 FMA (Blackwell): d.lo += a.lo*b.lo ; d.hi += a.hi*b.hi
// ---------------------------------------------------------------------------
__device__ __forceinline__ void ffma2(unsigned long long& d,
                                      const unsigned long long a,
                                      const unsigned long long b) {
    asm("fma.rn.f32x2 %0, %1, %2, %0;" : "+l"(d) : "l"(a), "l"(b));
}

__device__ __forceinline__ float hsum2(unsigned long long v) {
    float lo, hi;
    asm("mov.b64 {%0, %1}, %2;" : "=f"(lo), "=f"(hi) : "l"(v));
    return lo + hi;
}

__device__ __forceinline__ float sigf(float x) {
    return __fdividef(1.0f, 1.0f + __expf(-x));
}
__device__ __forceinline__ float tanh_fast(float x) {
    return 1.0f - __fdividef(2.0f, 1.0f + __expf(2.0f * x));
}

// ---------------------------------------------------------------------------
// Kernel 1: xg[r][g] = x[r][:] . W_ih[g][:] + b_ih[g] + (g<256 ? b_hh[g] : 0)
// 64-row x 96-col tiles, 2 blocks/SM (R5/R9 config — measured ~625us).
// ---------------------------------------------------------------------------
__global__ void __launch_bounds__(256, 2)
xg_gemm(const float* __restrict__ x,
        const float* __restrict__ Wih,
        const float* __restrict__ bih,
        const float* __restrict__ bhh) {
    __shared__ __align__(16) float xs[64 * 64];   // [row][k]
    __shared__ __align__(16) float ws[96 * 68];   // [col][k] padded

    const int tid = threadIdx.x;
    const int r0 = blockIdx.x * 64;
    const int cb = blockIdx.y;       // 0..3 -> 96 gate-cols each

    {
        const float4* xg4 = (const float4*)(x + (size_t)r0 * 64);
        float4* xs4 = (float4*)xs;
        #pragma unroll
        for (int i = tid; i < 64 * 16; i += 256) xs4[i] = xg4[i];
    }
    {
        const float4* wg4 = (const float4*)(Wih + (size_t)cb * 96 * 64);
        #pragma unroll
        for (int i = tid; i < 96 * 16; i += 256) {
            int g = i >> 4, k4 = i & 15;
            *(float4*)(ws + g * 68 + k4 * 4) = wg4[i];
        }
    }
    __syncthreads();

    const int ry = tid >> 4;   // 0..15 -> rows ry*4 .. +4
    const int cx = tid & 15;   // cols cx + 16*jj

    unsigned long long acc[4][6];
    #pragma unroll
    for (int i = 0; i < 4; i++)
        #pragma unroll
        for (int jj = 0; jj < 6; jj++) acc[i][jj] = 0ULL;

    #pragma unroll
    for (int k4 = 0; k4 < 16; k4++) {
        ulonglong2 wv[6];
        #pragma unroll
        for (int jj = 0; jj < 6; jj++)
            wv[jj] = *(const ulonglong2*)(ws + (cx + 16 * jj) * 68 + k4 * 4);
        #pragma unroll
        for (int i = 0; i < 4; i++) {
            ulonglong2 xv = *(const ulonglong2*)(xs + (ry * 4 + i) * 64 + k4 * 4);
            #pragma unroll
            for (int jj = 0; jj < 6; jj++) {
                ffma2(acc[i][jj], xv.x, wv[jj].x);
                ffma2(acc[i][jj], xv.y, wv[jj].y);
            }
        }
    }

    #pragma unroll
    for (int jj = 0; jj < 6; jj++) {
        const int g = cb * 96 + cx + 16 * jj;
        const float bias = bih[g] + (g < 256 ? bhh[g] : 0.0f);
        #pragma unroll
        for (int i = 0; i < 4; i++) {
            const int r = r0 + ry * 4 + i;
            g_xg[(size_t)r * G3 + g] = hsum2(acc[i][jj]) + bias;
        }
    }
}

// ---------------------------------------------------------------------------
// Kernel 2: GRU recurrence + final FC.
// 256 blocks x 2 batches, 256 threads, 2 blocks/SM (16 warps/SM).
// Thread: j = tid>>1 (hidden unit), half = tid&1 (k-half).
// r,z gate W row-halves in REGISTERS (64 regs); n gate row-half in smem
// (per-thread packed [tid][68], conflict-free). h double-buffered; one
// barrier/step; cross-half reduction via shfl_xor(.,1); thread finalizes
// gates for batch b = half.
// ---------------------------------------------------------------------------
#define HROW 136
__device__ __forceinline__ int hpos(int k) { return k + ((k >> 6) << 2); }

// dynamic smem (floats)
#define SM_WN    0                      // [256][68] = 17408 floats
#define SM_HS    (256 * 68)             // [2][2][HROW] = 544 floats
#define G_SM_FLOATS (SM_HS + 2 * 2 * HROW)
#define G_SM_BYTES  (G_SM_FLOATS * 4)

__global__ void __launch_bounds__(256, 2)
gru_kernel(const float* __restrict__ Whh,
           const float* __restrict__ bhh,
           const float* __restrict__ Wfc,
           const float* __restrict__ bfc,
           float* __restrict__ out) {
    extern __shared__ __align__(16) float sm[];
    float* wn_s = sm + SM_WN;
    float* hs = sm + SM_HS;

    const int tid = threadIdx.x;
    const int j = tid >> 1;
    const int half = tid & 1;
    const int b0 = blockIdx.x * 2;

    // n-gate W_hh row-half -> per-thread packed smem [tid][68]
    {
        const float4* src = (const float4*)(Whh + (size_t)(256 + j) * 128 + half * 64);
        #pragma unroll
        for (int kk = 0; kk < 16; kk++)
            *(float4*)(wn_s + tid * 68 + kk * 4) = src[kk];
    }
    for (int i = tid; i < 2 * HROW; i += 256) hs[i] = 0.0f;

    // r,z gate W row-halves -> registers (2 x 16 ull2 = 64 regs)
    ulonglong2 wrr[16], wzr[16];
    {
        const ulonglong2* wr_g = (const ulonglong2*)(Whh + (size_t)j * 128 + half * 64);
        const ulonglong2* wz_g = (const ulonglong2*)(Whh + (size_t)(j + 128) * 128 + half * 64);
        #pragma unroll
        for (int kk = 0; kk < 16; kk++) {
            wrr[kk] = wr_g[kk];
            wzr[kk] = wz_g[kk];
        }
    }
    const float bn = bhh[256 + j];   // n-gate hidden bias (inside r*(...))
    float hold = 0.0f;               // own h[j] for batch b0+half

    // xg row pointer for this thread's batch (b0+half), unit j
    const float* xp = g_xg + ((size_t)(b0 + half) * Tn) * G3 + j;
    const ulonglong2* wnp = (const ulonglong2*)(wn_s + tid * 68);

    __syncthreads();

    for (int t = 0; t < Tn; t++) {
        const float* hrd = hs + (t & 1) * (2 * HROW);
        float* hwr = hs + ((t & 1) ^ 1) * (2 * HROW);

        // Prefetch this thread's batch input projections (hidden under dot)
        const float xr = xp[0], xz = xp[128], xn = xp[256];
        xp += G3;

        unsigned long long acc[3][2];
        #pragma unroll
        for (int g = 0; g < 3; g++)
            #pragma unroll
            for (int b = 0; b < 2; b++) acc[g][b] = 0ULL;

        const float* hbase = hrd + half * 68;
        #pragma unroll
        for (int kk = 0; kk < 16; kk++) {
            const ulonglong2 wr = wrr[kk], wz = wzr[kk];
            const ulonglong2 wn = wnp[kk];
            #pragma unroll
            for (int b = 0; b < 2; b++) {
                ulonglong2 hv = *(const ulonglong2*)(hbase + b * HROW + kk * 4);
                ffma2(acc[0][b], wr.x, hv.x); ffma2(acc[0][b], wr.y, hv.y);
                ffma2(acc[1][b], wz.x, hv.x); ffma2(acc[1][b], wz.y, hv.y);
                ffma2(acc[2][b], wn.x, hv.x); ffma2(acc[2][b], wn.y, hv.y);
            }
        }

        // Horizontal sums (6 per thread)
        float s[3][2];
        #pragma unroll
        for (int g = 0; g < 3; g++)
            #pragma unroll
            for (int b = 0; b < 2; b++) s[g][b] = hsum2(acc[g][b]);

        // Cross-half reduce-scatter with partner lane (tid^1): I keep my
        // partials for batch `half`, send partials for the partner's batch.
        float tot[3];
        #pragma unroll
        for (int g = 0; g < 3; g++) {
            float keepv = half ? s[g][1] : s[g][0];
            float sendv = half ? s[g][0] : s[g][1];
            tot[g] = keepv + __shfl_xor_sync(0xFFFFFFFFu, sendv, 1);
        }

        // Gates for (j, b = half)
        {
            float r = sigf(xr + tot[0]);
            float z = sigf(xz + tot[1]);
            float n = tanh_fast(fmaf(r, tot[2] + bn, xn));
            float hnew = fmaf(z, hold - n, n);   // (1-z)*n + z*h
            hold = hnew;
            hwr[half * HROW + hpos(j)] = hnew;
        }

        __syncthreads();
    }

    // Final h is in buffer 0 (t=1023 writes buf (1023+1)&1 = 0).
    // FC: out[b][o] = h_T[b] . W_fc[o] + b_fc[o]
    if (tid < 2 * 51) {
        const int b = tid / 51, o = tid % 51;
        float a = bfc[o];
        const float* wf = Wfc + o * 128;
        const float* hp = hs + b * HROW;
        #pragma unroll 8
        for (int k = 0; k < 128; k++) a = fmaf(hp[hpos(k)], wf[k], a);
        out[(b0 + b) * 51 + o] = a;
    }
}

// ---------------------------------------------------------------------------
// Launch
// ---------------------------------------------------------------------------
extern "C" void kernel_launch(void* const* d_in, const int* in_sizes, int n_in,
                              void* d_out, int out_size) {
    const float* x    = (const float*)d_in[0];  // [512,1,1024,64]
    const float* Wih  = (const float*)d_in[1];  // [384,64]
    const float* Whh  = (const float*)d_in[2];  // [384,128]
    const float* bih  = (const float*)d_in[3];  // [384]
    const float* bhh  = (const float*)d_in[4];  // [384]
    const float* Wfc  = (const float*)d_in[5];  // [51,128]
    const float* bfc  = (const float*)d_in[6];  // [51]
    float* out = (float*)d_out;                 // [512,51]

    static int attr_done = 0;
    if (!attr_done) {
        cudaFuncSetAttribute(gru_kernel,
                             cudaFuncAttributeMaxDynamicSharedMemorySize,
                             G_SM_BYTES);
        attr_done = 1;
    }

    xg_gemm<<<dim3((Bn * Tn) / 64, 4, 1), 256>>>(x, Wih, bih, bhh);
    gru_kernel<<<256, 256, G_SM_BYTES>>>(Whh, bhh, Wfc, bfc, out);
}

// round 12
// speedup vs baseline: 1.8985x; 1.7956x over previous
#include <cuda_runtime.h>
#include <cstdint>
#include <cstddef>

#define Tn 1024
#define Bn 512
#define Hn 128
#define In 64
#define G3 384

// 805 MB scratch for precomputed input-side gate projections: xg[b][t][g]
__device__ float g_xg[(size_t)Bn * Tn * G3];

// ---------------------------------------------------------------------------
// Packed f32x2 FMA (Blackwell): d.lo += a.lo*b.lo ; d.hi += a.hi*b.hi
// ---------------------------------------------------------------------------
__device__ __forceinline__ void ffma2(unsigned long long& d,
                                      const unsigned long long a,
                                      const unsigned long long b) {
    asm("fma.rn.f32x2 %0, %1, %2, %0;" : "+l"(d) : "l"(a), "l"(b));
}

__device__ __forceinline__ float hsum2(unsigned long long v) {
    float lo, hi;
    asm("mov.b64 {%0, %1}, %2;" : "=f"(lo), "=f"(hi) : "l"(v));
    return lo + hi;
}

__device__ __forceinline__ float sigf(float x) {
    return __fdividef(1.0f, 1.0f + __expf(-x));
}
__device__ __forceinline__ float tanh_fast(float x) {
    return 1.0f - __fdividef(2.0f, 1.0f + __expf(2.0f * x));
}

// ---------------------------------------------------------------------------
// Kernel 1: xg[r][g] = x[r][:] . W_ih[g][:] + b_ih[g] + (g<256 ? b_hh[g] : 0)
// 64-row x 96-col tiles, 2 blocks/SM (R5/R9 config — measured ~625us).
// ---------------------------------------------------------------------------
__global__ void __launch_bounds__(256, 2)
xg_gemm(const float* __restrict__ x,
        const float* __restrict__ Wih,
        const float* __restrict__ bih,
        const float* __restrict__ bhh) {
    __shared__ __align__(16) float xs[64 * 64];   // [row][k]
    __shared__ __align__(16) float ws[96 * 68];   // [col][k] padded

    const int tid = threadIdx.x;
    const int r0 = blockIdx.x * 64;
    const int cb = blockIdx.y;       // 0..3 -> 96 gate-cols each

    {
        const float4* xg4 = (const float4*)(x + (size_t)r0 * 64);
        float4* xs4 = (float4*)xs;
        #pragma unroll
        for (int i = tid; i < 64 * 16; i += 256) xs4[i] = xg4[i];
    }
    {
        const float4* wg4 = (const float4*)(Wih + (size_t)cb * 96 * 64);
        #pragma unroll
        for (int i = tid; i < 96 * 16; i += 256) {
            int g = i >> 4, k4 = i & 15;
            *(float4*)(ws + g * 68 + k4 * 4) = wg4[i];
        }
    }
    __syncthreads();

    const int ry = tid >> 4;   // 0..15 -> rows ry*4 .. +4
    const int cx = tid & 15;   // cols cx + 16*jj

    unsigned long long acc[4][6];
    #pragma unroll
    for (int i = 0; i < 4; i++)
        #pragma unroll
        for (int jj = 0; jj < 6; jj++) acc[i][jj] = 0ULL;

    #pragma unroll
    for (int k4 = 0; k4 < 16; k4++) {
        ulonglong2 wv[6];
        #pragma unroll
        for (int jj = 0; jj < 6; jj++)
            wv[jj] = *(const ulonglong2*)(ws + (cx + 16 * jj) * 68 + k4 * 4);
        #pragma unroll
        for (int i = 0; i < 4; i++) {
            ulonglong2 xv = *(const ulonglong2*)(xs + (ry * 4 + i) * 64 + k4 * 4);
            #pragma unroll
            for (int jj = 0; jj < 6; jj++) {
                ffma2(acc[i][jj], xv.x, wv[jj].x);
                ffma2(acc[i][jj], xv.y, wv[jj].y);
            }
        }
    }

    #pragma unroll
    for (int jj = 0; jj < 6; jj++) {
        const int g = cb * 96 + cx + 16 * jj;
        const float bias = bih[g] + (g < 256 ? bhh[g] : 0.0f);
        #pragma unroll
        for (int i = 0; i < 4; i++) {
            const int r = r0 + ry * 4 + i;
            g_xg[(size_t)r * G3 + g] = hsum2(acc[i][jj]) + bias;
        }
    }
}

// ---------------------------------------------------------------------------
// Kernel 2: GRU recurrence + final FC.
// 128 blocks x 4 batches, 256 threads, 1 block/SM (full 255-reg envelope).
// Thread: j = tid>>1, half = tid&1. r,z gate W row-halves in REGISTERS
// (128 regs); n gate row-half in per-thread-packed smem [tid][68]
// (conflict-free phases) -> frees 64 regs of scheduling headroom vs R9.
// h double-buffered; 1 barrier/step; cross-half reduction via shfl_xor(.,1).
// ---------------------------------------------------------------------------
#define HROW 136
__device__ __forceinline__ int hpos(int k) { return k + ((k >> 6) << 2); }

// dynamic smem (floats)
#define SM_WN    0                      // [256][68] = 17408 floats
#define SM_HS    (256 * 68)             // [2][4][HROW] = 1088 floats
#define G_SM_FLOATS (SM_HS + 2 * 4 * HROW)
#define G_SM_BYTES  (G_SM_FLOATS * 4)

__global__ void __launch_bounds__(256, 1)
gru_kernel(const float* __restrict__ Whh,
           const float* __restrict__ bhh,
           const float* __restrict__ Wfc,
           const float* __restrict__ bfc,
           float* __restrict__ out) {
    extern __shared__ __align__(16) float sm[];
    float* wn_s = sm + SM_WN;
    float* hs = sm + SM_HS;

    const int tid = threadIdx.x;
    const int j = tid >> 1;
    const int half = tid & 1;
    const int b0 = blockIdx.x * 4;

    // n-gate W_hh row-half -> per-thread packed smem [tid][68]
    {
        const float4* src = (const float4*)(Whh + (size_t)(256 + j) * 128 + half * 64);
        #pragma unroll
        for (int kk = 0; kk < 16; kk++)
            *(float4*)(wn_s + tid * 68 + kk * 4) = src[kk];
    }
    for (int i = tid; i < 4 * HROW; i += 256) hs[i] = 0.0f;

    // r,z gate W row-halves -> registers (2 x 16 ull2 = 128 regs)
    ulonglong2 wrr[16], wzr[16];
    {
        const ulonglong2* wr_g = (const ulonglong2*)(Whh + (size_t)j * 128 + half * 64);
        const ulonglong2* wz_g = (const ulonglong2*)(Whh + (size_t)(j + 128) * 128 + half * 64);
        #pragma unroll
        for (int kk = 0; kk < 16; kk++) {
            wrr[kk] = wr_g[kk];
            wzr[kk] = wz_g[kk];
        }
    }
    const float bn = bhh[256 + j];
    float hold[2] = {0.f, 0.f};

    const size_t xgA = ((size_t)(b0 + 2 * half) * Tn) * G3 + j;
    const size_t xgB = ((size_t)(b0 + 2 * half + 1) * Tn) * G3 + j;
    const ulonglong2* wnp = (const ulonglong2*)(wn_s + tid * 68);

    __syncthreads();

    for (int t = 0; t < Tn; t++) {
        const float* hrd = hs + (t & 1) * (4 * HROW);
        float* hwr = hs + ((t & 1) ^ 1) * (4 * HROW);

        // Prefetch this thread's 2 batches' input projections
        const float* xpA = g_xg + xgA + (size_t)t * G3;
        const float* xpB = g_xg + xgB + (size_t)t * G3;
        float xr0 = xpA[0], xz0 = xpA[128], xn0 = xpA[256];
        float xr1 = xpB[0], xz1 = xpB[128], xn1 = xpB[256];

        unsigned long long acc[3][4];
        #pragma unroll
        for (int g = 0; g < 3; g++)
            #pragma unroll
            for (int b = 0; b < 4; b++) acc[g][b] = 0ULL;

        const float* hbase = hrd + half * 68;
        #pragma unroll
        for (int kk = 0; kk < 16; kk++) {
            const ulonglong2 wr = wrr[kk], wz = wzr[kk];
            const ulonglong2 wn = wnp[kk];
            #pragma unroll
            for (int b = 0; b < 4; b++) {
                ulonglong2 hv = *(const ulonglong2*)(hbase + b * HROW + kk * 4);
                ffma2(acc[0][b], wr.x, hv.x); ffma2(acc[0][b], wr.y, hv.y);
                ffma2(acc[1][b], wz.x, hv.x); ffma2(acc[1][b], wz.y, hv.y);
                ffma2(acc[2][b], wn.x, hv.x); ffma2(acc[2][b], wn.y, hv.y);
            }
        }

        float s[3][4];
        #pragma unroll
        for (int g = 0; g < 3; g++)
            #pragma unroll
            for (int b = 0; b < 4; b++) s[g][b] = hsum2(acc[g][b]);

        // Cross-half reduce-scatter with partner lane (tid^1)
        float tot[3][2];
        #pragma unroll
        for (int g = 0; g < 3; g++) {
            #pragma unroll
            for (int i = 0; i < 2; i++) {
                float keepv = half ? s[g][2 + i] : s[g][i];
                float sendv = half ? s[g][i] : s[g][2 + i];
                tot[g][i] = keepv + __shfl_xor_sync(0xFFFFFFFFu, sendv, 1);
            }
        }

        {
            float r0g = sigf(xr0 + tot[0][0]);
            float z0g = sigf(xz0 + tot[1][0]);
            float n0g = tanh_fast(fmaf(r0g, tot[2][0] + bn, xn0));
            float h0n = fmaf(z0g, hold[0] - n0g, n0g);
            hold[0] = h0n;
            hwr[(2 * half + 0) * HROW + hpos(j)] = h0n;

            float r1g = sigf(xr1 + tot[0][1]);
            float z1g = sigf(xz1 + tot[1][1]);
            float n1g = tanh_fast(fmaf(r1g, tot[2][1] + bn, xn1));
            float h1n = fmaf(z1g, hold[1] - n1g, n1g);
            hold[1] = h1n;
            hwr[(2 * half + 1) * HROW + hpos(j)] = h1n;
        }

        __syncthreads();
    }

    // Final h is in buffer 0. FC: out[b][o] = h_T[b] . W_fc[o] + b_fc[o]
    if (tid < 4 * 51) {
        const int b = tid / 51, o = tid % 51;
        float a = bfc[o];
        const float* wf = Wfc + o * 128;
        const float* hp = hs + b * HROW;
        #pragma unroll 8
        for (int k = 0; k < 128; k++) a = fmaf(hp[hpos(k)], wf[k], a);
        out[(b0 + b) * 51 + o] = a;
    }
}

// ---------------------------------------------------------------------------
// Launch
// ---------------------------------------------------------------------------
extern "C" void kernel_launch(void* const* d_in, const int* in_sizes, int n_in,
                              void* d_out, int out_size) {
    const float* x    = (const float*)d_in[0];  // [512,1,1024,64]
    const float* Wih  = (const float*)d_in[1];  // [384,64]
    const float* Whh  = (const float*)d_in[2];  // [384,128]
    const float* bih  = (const float*)d_in[3];  // [384]
    const float* bhh  = (const float*)d_in[4];  // [384]
    const float* Wfc  = (const float*)d_in[5];  // [51,128]
    const float* bfc  = (const float*)d_in[6];  // [51]
    float* out = (float*)d_out;                 // [512,51]

    static int attr_done = 0;
    if (!attr_done) {
        cudaFuncSetAttribute(gru_kernel,
                             cudaFuncAttributeMaxDynamicSharedMemorySize,
                             G_SM_BYTES);
        attr_done = 1;
    }

    xg_gemm<<<dim3((Bn * Tn) / 64, 4, 1), 256>>>(x, Wih, bih, bhh);
    gru_kernel<<<128, 256, G_SM_BYTES>>>(Whh, bhh, Wfc, bfc, out);
}